// round 12
// baseline (speedup 1.0000x reference)
#include <cuda_runtime.h>
#include <cuda_fp16.h>
#include <cstdint>

#define T_DIM 4096
#define NUM_TILES 2048
#define THREADS 288          // 8 consumer warps + 1 producer warp

// ---- shared memory layout (bytes) ----
// VF: v_tp fp16 fragment-packed: [ksg(16)][J(8)][lane(32)][16B = nb-even 8B | nb-odd 8B]
#define VF_OFF 0
// A: double-buffered fp32 chunk: [buf(2)][row(128)][8 x 16B cells, cell ^= (row&1)<<2]
#define A_OFF  65536
#define A_BUF_BYTES 16384
#define W_OFF  98304
#define SC_OFF 98816
#define MB_OFF 99328         // full[2] @ +0,+8 ; free[2] @ +16,+24
#define SMEM_BYTES 99456

__device__ __forceinline__ uint32_t pack2h(float lo, float hi) {
    uint32_t r;
    asm("cvt.rn.f16x2.f32 %0, %1, %2;" : "=r"(r) : "f"(hi), "f"(lo));
    return r;
}

__device__ __forceinline__ float tanh_fast(float x) {
    float r;
    asm("tanh.approx.f32 %0, %1;" : "=f"(r) : "f"(x));
    return r;
}

__device__ __forceinline__ void sts64(uint32_t addr, uint32_t a, uint32_t b) {
    asm volatile("st.shared.v2.b32 [%0], {%1,%2};" :: "r"(addr), "r"(a), "r"(b) : "memory");
}

__device__ __forceinline__ void lds128(uint32_t* r, uint32_t addr) {
    asm volatile("ld.shared.v4.b32 {%0,%1,%2,%3}, [%4];"
                 : "=r"(r[0]), "=r"(r[1]), "=r"(r[2]), "=r"(r[3]) : "r"(addr));
}

__device__ __forceinline__ void mma16(float* c, const uint32_t* a, uint32_t b0, uint32_t b1) {
    asm volatile(
        "mma.sync.aligned.m16n8k16.row.col.f32.f16.f16.f32 "
        "{%0,%1,%2,%3}, {%4,%5,%6,%7}, {%8,%9}, {%0,%1,%2,%3};\n"
        : "+f"(c[0]), "+f"(c[1]), "+f"(c[2]), "+f"(c[3])
        : "r"(a[0]), "r"(a[1]), "r"(a[2]), "r"(a[3]), "r"(b0), "r"(b1));
}

__device__ __forceinline__ void cp_async16(uint32_t saddr, const void* g) {
    asm volatile("cp.async.cg.shared.global [%0], [%1], 16;\n" :: "r"(saddr), "l"(g));
}

__device__ __forceinline__ void cp_async_mbar_arrive(uint32_t mbar) {
    asm volatile("cp.async.mbarrier.arrive.noinc.shared.b64 [%0];" :: "r"(mbar) : "memory");
}

__device__ __forceinline__ void mbar_init(uint32_t addr, uint32_t cnt) {
    asm volatile("mbarrier.init.shared.b64 [%0], %1;" :: "r"(addr), "r"(cnt) : "memory");
}
__device__ __forceinline__ void mbar_arrive(uint32_t addr) {
    asm volatile("mbarrier.arrive.shared.b64 _, [%0];" :: "r"(addr) : "memory");
}
__device__ __forceinline__ void mbar_wait(uint32_t addr, uint32_t parity) {
    uint32_t done;
    asm volatile(
        "{\n\t.reg .pred p;\n\t"
        "mbarrier.try_wait.parity.acquire.cta.shared::cta.b64 p, [%1], %2;\n\t"
        "selp.b32 %0, 1, 0, p;\n\t}"
        : "=r"(done) : "r"(addr), "r"(parity) : "memory");
    if (!done) {
        asm volatile(
            "{\n\t.reg .pred P1;\n\t"
            "W0_%=:\n\t"
            "mbarrier.try_wait.parity.acquire.cta.shared::cta.b64 P1, [%0], %1, 0x989680;\n\t"
            "@P1 bra.uni W1_%=;\n\t"
            "bra.uni W0_%=;\n\t"
            "W1_%=:\n\t}"
            :: "r"(addr), "r"(parity) : "memory");
    }
}

__global__ void __launch_bounds__(THREADS, 2)
topo_attention_v6(const float* __restrict__ h1,
                  const float* __restrict__ h2,
                  const float* __restrict__ w,
                  const float* __restrict__ v,
                  float* __restrict__ out) {
    extern __shared__ char smem[];
    uint32_t smem_u32;
    asm("{ .reg .u64 t; cvta.to.shared.u64 t, %1; cvt.u32.u64 %0, t; }"
        : "=r"(smem_u32) : "l"(smem));
    float* w_s  = (float*)(smem + W_OFF);
    float* sc_s = (float*)(smem + SC_OFF);

    const int tid  = threadIdx.x;
    const int wid  = tid >> 5;
    const int lane = tid & 31;
    const int bx = blockIdx.x;
    const int grid = gridDim.x;

    // ---- prologue: VF pack (fp16, K-permuted fragment layout), w, sc, mbarriers ----
    for (int i = tid * 4; i < 32768; i += THREADS * 4) {
        float4 vv = *(const float4*)(v + i);
        int l = i >> 8, m = i & 255;
        int ksg = m >> 4, tp = (m >> 2) & 3;
        int nb = l >> 3, gp = l & 7;
        uint32_t addr = smem_u32 + VF_OFF +
            (uint32_t)(ksg * 4096 + (nb >> 1) * 512 + (gp * 4 + tp) * 16 + (nb & 1) * 8);
        sts64(addr, pack2h(vv.x, vv.y), pack2h(vv.z, vv.w));
    }
    if (tid < 128) { w_s[tid] = w[tid]; sc_s[tid] = 0.0f; }
    if (tid == 0) {
        mbar_init(smem_u32 + MB_OFF + 0, 32);   // full[0]
        mbar_init(smem_u32 + MB_OFF + 8, 32);   // full[1]
        mbar_init(smem_u32 + MB_OFF + 16, 8);   // free[0]
        mbar_init(smem_u32 + MB_OFF + 24, 8);   // free[1]
    }
    __syncthreads();

    int ntile = 0;
    for (int t = bx; t < NUM_TILES; t += grid) ntile++;
    const int NCH = ntile * 8;   // K=32 chunks

    if (wid == 8) {
        // ================= producer warp =================
        const int rbase = lane >> 3;           // 0..3 (row within 4-row group)
        const int c     = lane & 7;            // 16B cell within row
        const int par_p = rbase & 1;
        const float* hp = par_p ? h2 : h1;
        const uint32_t celloff = (uint32_t)((c ^ (par_p << 2)) << 4);

        for (int gc = 0; gc < NCH; ++gc) {
            int buf = gc & 1;
            if (gc >= 2) mbar_wait(smem_u32 + MB_OFF + 16 + buf * 8, ((gc >> 1) - 1) & 1);
            int tile = bx + (gc >> 3) * grid;
            int ck = gc & 7;
            uint32_t sbase = smem_u32 + A_OFF + (uint32_t)buf * A_BUF_BYTES + celloff;
            const float4* gbase = (const float4*)hp +
                (size_t)(tile * 64 + (rbase >> 1)) * 64 + ck * 8 + c;
            #pragma unroll
            for (int i = 0; i < 32; ++i) {
                // row = i*4 + rbase ; global pair-row advances by 2 per i
                cp_async16(sbase + (uint32_t)((i * 4 + rbase) * 128),
                           gbase + (size_t)i * 2 * 64);
            }
            cp_async_mbar_arrive(smem_u32 + MB_OFF + buf * 8);
        }
    } else {
        // ================= 8 consumer warps: 4m x 2n =================
        const int warp_m = wid >> 1;
        const int warp_n = wid & 1;
        const int g   = lane >> 2;
        const int tig = lane & 3;
        const int par = g & 1;

        const uint32_t vb = smem_u32 + VF_OFF + (uint32_t)(warp_n * 2048 + lane * 16);
        uint32_t arow[2][2];
        #pragma unroll
        for (int mt = 0; mt < 2; ++mt) {
            int row_lo = warp_m * 32 + mt * 16 + g;
            arow[mt][0] = (uint32_t)(row_lo * 128);
            arow[mt][1] = (uint32_t)((row_lo + 8) * 128);
        }

        float acc[2][8][4];
        #pragma unroll
        for (int mt = 0; mt < 2; mt++)
            #pragma unroll
            for (int nt = 0; nt < 8; nt++)
                #pragma unroll
                for (int i = 0; i < 4; i++) acc[mt][nt][i] = 0.0f;

        for (int gc = 0; gc < NCH; ++gc) {
            int buf = gc & 1;
            mbar_wait(smem_u32 + MB_OFF + buf * 8, (gc >> 1) & 1);
            uint32_t ab = smem_u32 + A_OFF + (uint32_t)buf * A_BUF_BYTES;

            #pragma unroll
            for (int ks = 0; ks < 2; ++ks) {
                int ksg = (gc & 7) * 2 + ks;
                uint32_t bb[4][4];
                #pragma unroll
                for (int jj = 0; jj < 4; ++jj)
                    lds128(bb[jj], vb + (uint32_t)(ksg * 4096 + jj * 512));

                int kx = par ? (1 - ks) : ks;
                uint32_t coff = (uint32_t)((kx * 4 + tig) << 4);
                uint32_t afr[2][4];
                #pragma unroll
                for (int mt = 0; mt < 2; ++mt) {
                    uint32_t lo[4], hi[4];
                    lds128(lo, ab + arow[mt][0] + coff);
                    lds128(hi, ab + arow[mt][1] + coff);
                    afr[mt][0] = pack2h(__uint_as_float(lo[0]), __uint_as_float(lo[1]));
                    afr[mt][1] = pack2h(__uint_as_float(hi[0]), __uint_as_float(hi[1]));
                    afr[mt][2] = pack2h(__uint_as_float(lo[2]), __uint_as_float(lo[3]));
                    afr[mt][3] = pack2h(__uint_as_float(hi[2]), __uint_as_float(hi[3]));
                }
                #pragma unroll
                for (int mt = 0; mt < 2; ++mt)
                    #pragma unroll
                    for (int jj = 0; jj < 4; ++jj) {
                        mma16(acc[mt][2 * jj],     afr[mt], bb[jj][0], bb[jj][1]);
                        mma16(acc[mt][2 * jj + 1], afr[mt], bb[jj][2], bb[jj][3]);
                    }
            }
            if (lane == 0) mbar_arrive(smem_u32 + MB_OFF + 16 + buf * 8);

            if ((gc & 7) == 7) {
                // ---- epilogue for tile = bx + (gc>>3)*grid ----
                int tile = bx + (gc >> 3) * grid;
                float part[4];
                #pragma unroll
                for (int mt = 0; mt < 2; ++mt) {
                    float p0 = 0.f, p1 = 0.f;
                    #pragma unroll
                    for (int nt = 0; nt < 8; ++nt) {
                        int l0 = warp_n * 64 + nt * 8 + tig * 2;
                        float w0 = w_s[l0], w1 = w_s[l0 + 1];
                        p0 += w0 * tanh_fast(acc[mt][nt][0]) + w1 * tanh_fast(acc[mt][nt][1]);
                        p1 += w0 * tanh_fast(acc[mt][nt][2]) + w1 * tanh_fast(acc[mt][nt][3]);
                        #pragma unroll
                        for (int i = 0; i < 4; i++) acc[mt][nt][i] = 0.0f;
                    }
                    part[mt * 2] = p0;
                    part[mt * 2 + 1] = p1;
                }
                #pragma unroll
                for (int i = 0; i < 4; i++) {
                    part[i] += __shfl_xor_sync(0xffffffffu, part[i], 1);
                    part[i] += __shfl_xor_sync(0xffffffffu, part[i], 2);
                }
                if (tig == 0) {
                    #pragma unroll
                    for (int i = 0; i < 4; i++) {
                        int row = warp_m * 32 + (i >> 1) * 16 + (i & 1) * 8 + g;
                        atomicAdd(&sc_s[row], part[i]);
                    }
                }
                asm volatile("bar.sync 1, 256;" ::: "memory");
                if (tid < 64) {
                    float s0 = sc_s[2 * tid];
                    float s1 = sc_s[2 * tid + 1];
                    sc_s[2 * tid] = 0.0f;
                    sc_s[2 * tid + 1] = 0.0f;
                    int P = tile * 64 + tid;            // global (b*T + t)
                    int b = P >> 12;
                    int t = P & 4095;
                    float a0 = 1.0f / (1.0f + __expf(s1 - s0));
                    out[((b * 2) + 0) * T_DIM + t] = a0;
                    out[((b * 2) + 1) * T_DIM + t] = 1.0f - a0;
                }
                asm volatile("bar.sync 1, 256;" ::: "memory");
            }
        }
    }
}

extern "C" void kernel_launch(void* const* d_in, const int* in_sizes, int n_in,
                              void* d_out, int out_size) {
    const float* h1 = (const float*)d_in[0];
    const float* h2 = (const float*)d_in[1];
    const float* w  = (const float*)d_in[2];
    const float* v  = (const float*)d_in[3];
    float* out = (float*)d_out;

    cudaFuncSetAttribute(topo_attention_v6,
                         cudaFuncAttributeMaxDynamicSharedMemorySize, SMEM_BYTES);

    int nsm = 148;
    if (cudaDeviceGetAttribute(&nsm, cudaDevAttrMultiProcessorCount, 0) != cudaSuccess || nsm <= 0)
        nsm = 148;

    topo_attention_v6<<<2 * nsm, THREADS, SMEM_BYTES>>>(h1, h2, w, v, out);
}

// round 14
// speedup vs baseline: 1.4840x; 1.4840x over previous
#include <cuda_runtime.h>
#include <cuda_fp16.h>
#include <cstdint>

#define T_DIM 4096
#define NUM_TILES 2048
#define THREADS 256

// ---- shared memory layout (bytes) ----
// VF: v_tp fp16 fragment-packed: [ksg(16)][J(8)][lane(32)][16B = nb-even 8B | nb-odd 8B]
#define VF_OFF 0
// A: 3-stage ring of fp32 K=32 chunks: [stage(3)][row(128)][8 x 16B cells, cell ^= (row&1)<<2]
#define A_OFF  65536
#define A_BUF_BYTES 16384
#define W_OFF  114688
#define SC_OFF 115200
#define SMEM_BYTES 115712

__device__ __forceinline__ uint32_t pack2h(float lo, float hi) {
    uint32_t r;
    asm("cvt.rn.f16x2.f32 %0, %1, %2;" : "=r"(r) : "f"(hi), "f"(lo));
    return r;
}

__device__ __forceinline__ float tanh_fast(float x) {
    float r;
    asm("tanh.approx.f32 %0, %1;" : "=f"(r) : "f"(x));
    return r;
}

__device__ __forceinline__ void sts64(uint32_t addr, uint32_t a, uint32_t b) {
    asm volatile("st.shared.v2.b32 [%0], {%1,%2};" :: "r"(addr), "r"(a), "r"(b) : "memory");
}

__device__ __forceinline__ void lds128(uint32_t* r, uint32_t addr) {
    asm volatile("ld.shared.v4.b32 {%0,%1,%2,%3}, [%4];"
                 : "=r"(r[0]), "=r"(r[1]), "=r"(r[2]), "=r"(r[3]) : "r"(addr));
}

__device__ __forceinline__ void mma16(float* c, const uint32_t* a, uint32_t b0, uint32_t b1) {
    asm volatile(
        "mma.sync.aligned.m16n8k16.row.col.f32.f16.f16.f32 "
        "{%0,%1,%2,%3}, {%4,%5,%6,%7}, {%8,%9}, {%0,%1,%2,%3};\n"
        : "+f"(c[0]), "+f"(c[1]), "+f"(c[2]), "+f"(c[3])
        : "r"(a[0]), "r"(a[1]), "r"(a[2]), "r"(a[3]), "r"(b0), "r"(b1));
}

__device__ __forceinline__ void cp_async16(uint32_t saddr, const void* g) {
    asm volatile("cp.async.cg.shared.global [%0], [%1], 16;\n" :: "r"(saddr), "l"(g));
}

// issue one K=32 chunk (16KB) cooperatively: 4 cp.async16 per thread, then commit
__device__ __forceinline__ void issue_chunk(int gc, int tid, uint32_t smem_u32,
                                            const float* h1, const float* h2,
                                            int bx, int grid) {
    int tile = bx + (gc >> 3) * grid;
    int ck = gc & 7;
    uint32_t sbase = smem_u32 + A_OFF + (uint32_t)(gc % 3) * A_BUF_BYTES;
    #pragma unroll
    for (int i = 0; i < 4; ++i) {
        int idx = i * THREADS + tid;       // 0..1023
        int row = idx >> 3;                // 0..127
        int cell = idx & 7;                // 16B cell within 128B row
        int dcell = cell ^ ((row & 1) << 2);
        const float* hp = (row & 1) ? h2 : h1;
        const float4* src = (const float4*)hp
                            + (size_t)(tile * 64 + (row >> 1)) * 64 + ck * 8 + cell;
        cp_async16(sbase + (uint32_t)(row * 128 + dcell * 16), src);
    }
    asm volatile("cp.async.commit_group;" ::: "memory");
}

__global__ void __launch_bounds__(THREADS, 2)
topo_attention_v7(const float* __restrict__ h1,
                  const float* __restrict__ h2,
                  const float* __restrict__ w,
                  const float* __restrict__ v,
                  float* __restrict__ out) {
    extern __shared__ char smem[];
    uint32_t smem_u32;
    asm("{ .reg .u64 t; cvta.to.shared.u64 t, %1; cvt.u32.u64 %0, t; }"
        : "=r"(smem_u32) : "l"(smem));
    float* w_s  = (float*)(smem + W_OFF);
    float* sc_s = (float*)(smem + SC_OFF);

    const int tid  = threadIdx.x;
    const int wid  = tid >> 5;
    const int lane = tid & 31;
    const int bx = blockIdx.x;
    const int grid = gridDim.x;

    // ---- prologue: VF pack (fp16, K-permuted fragment layout), w, sc ----
    for (int i = tid * 4; i < 32768; i += THREADS * 4) {
        float4 vv = *(const float4*)(v + i);
        int l = i >> 8, m = i & 255;
        int ksg = m >> 4, tp = (m >> 2) & 3;
        int nb = l >> 3, gp = l & 7;
        uint32_t addr = smem_u32 + VF_OFF +
            (uint32_t)(ksg * 4096 + (nb >> 1) * 512 + (gp * 4 + tp) * 16 + (nb & 1) * 8);
        sts64(addr, pack2h(vv.x, vv.y), pack2h(vv.z, vv.w));
    }
    if (tid < 128) { w_s[tid] = w[tid]; sc_s[tid] = 0.0f; }
    __syncthreads();

    int ntile = 0;
    for (int t = bx; t < NUM_TILES; t += grid) ntile++;
    const int NCH = ntile * 8;   // K=32 chunks

    // consumer constants: 8 warps = 4m x 2n
    const int warp_m = wid >> 1;
    const int warp_n = wid & 1;
    const int g   = lane >> 2;
    const int tig = lane & 3;
    const int par = g & 1;

    const uint32_t vb = smem_u32 + VF_OFF + (uint32_t)(warp_n * 2048 + lane * 16);
    uint32_t arow[2][2];
    #pragma unroll
    for (int mt = 0; mt < 2; ++mt) {
        int row_lo = warp_m * 32 + mt * 16 + g;
        arow[mt][0] = (uint32_t)(row_lo * 128);
        arow[mt][1] = (uint32_t)((row_lo + 8) * 128);
    }

    float acc[2][8][4];
    #pragma unroll
    for (int mt = 0; mt < 2; mt++)
        #pragma unroll
        for (int nt = 0; nt < 8; nt++)
            #pragma unroll
            for (int i = 0; i < 4; i++) acc[mt][nt][i] = 0.0f;

    // prime pipeline: stages 0,1
    issue_chunk(0, tid, smem_u32, h1, h2, bx, grid);
    if (NCH > 1) issue_chunk(1, tid, smem_u32, h1, h2, bx, grid);

    for (int gc = 0; gc < NCH; ++gc) {
        // Drain rule: the most recent commit is chunk min(gc+1, NCH-1).
        // wait_group 1 guarantees chunk gc ONLY while gc+1 <= NCH-1; on the
        // final iteration the newest commit IS chunk gc, so drain fully.
        if (gc + 1 < NCH) {
            asm volatile("cp.async.wait_group 1;" ::: "memory");
        } else {
            asm volatile("cp.async.wait_group 0;" ::: "memory");
        }
        __syncthreads();   // chunk gc arrived AND all warps done with MMA(gc-1)

        if (gc + 2 < NCH) issue_chunk(gc + 2, tid, smem_u32, h1, h2, bx, grid);

        uint32_t ab = smem_u32 + A_OFF + (uint32_t)(gc % 3) * A_BUF_BYTES;
        #pragma unroll
        for (int ks = 0; ks < 2; ++ks) {
            int ksg = (gc & 7) * 2 + ks;
            uint32_t bb[4][4];
            #pragma unroll
            for (int jj = 0; jj < 4; ++jj)
                lds128(bb[jj], vb + (uint32_t)(ksg * 4096 + jj * 512));

            int kx = par ? (1 - ks) : ks;
            uint32_t coff = (uint32_t)((kx * 4 + tig) << 4);
            uint32_t afr[2][4];
            #pragma unroll
            for (int mt = 0; mt < 2; ++mt) {
                uint32_t lo[4], hi[4];
                lds128(lo, ab + arow[mt][0] + coff);
                lds128(hi, ab + arow[mt][1] + coff);
                afr[mt][0] = pack2h(__uint_as_float(lo[0]), __uint_as_float(lo[1]));
                afr[mt][1] = pack2h(__uint_as_float(hi[0]), __uint_as_float(hi[1]));
                afr[mt][2] = pack2h(__uint_as_float(lo[2]), __uint_as_float(lo[3]));
                afr[mt][3] = pack2h(__uint_as_float(hi[2]), __uint_as_float(hi[3]));
            }
            #pragma unroll
            for (int mt = 0; mt < 2; ++mt)
                #pragma unroll
                for (int jj = 0; jj < 4; ++jj) {
                    mma16(acc[mt][2 * jj],     afr[mt], bb[jj][0], bb[jj][1]);
                    mma16(acc[mt][2 * jj + 1], afr[mt], bb[jj][2], bb[jj][3]);
                }
        }

        if ((gc & 7) == 7) {
            // ---- epilogue for tile = bx + (gc>>3)*grid ----
            int tile = bx + (gc >> 3) * grid;
            float part[4];
            #pragma unroll
            for (int mt = 0; mt < 2; ++mt) {
                float p0 = 0.f, p1 = 0.f;
                #pragma unroll
                for (int nt = 0; nt < 8; ++nt) {
                    int l0 = warp_n * 64 + nt * 8 + tig * 2;
                    float w0 = w_s[l0], w1 = w_s[l0 + 1];
                    p0 += w0 * tanh_fast(acc[mt][nt][0]) + w1 * tanh_fast(acc[mt][nt][1]);
                    p1 += w0 * tanh_fast(acc[mt][nt][2]) + w1 * tanh_fast(acc[mt][nt][3]);
                    #pragma unroll
                    for (int i = 0; i < 4; i++) acc[mt][nt][i] = 0.0f;
                }
                part[mt * 2] = p0;
                part[mt * 2 + 1] = p1;
            }
            #pragma unroll
            for (int i = 0; i < 4; i++) {
                part[i] += __shfl_xor_sync(0xffffffffu, part[i], 1);
                part[i] += __shfl_xor_sync(0xffffffffu, part[i], 2);
            }
            if (tig == 0) {
                #pragma unroll
                for (int i = 0; i < 4; i++) {
                    int row = warp_m * 32 + (i >> 1) * 16 + (i & 1) * 8 + g;
                    atomicAdd(&sc_s[row], part[i]);
                }
            }
            __syncthreads();   // all atomicAdds visible
            if (tid < 64) {
                float s0 = sc_s[2 * tid];
                float s1 = sc_s[2 * tid + 1];
                sc_s[2 * tid] = 0.0f;
                sc_s[2 * tid + 1] = 0.0f;
                int P = tile * 64 + tid;            // global (b*T + t)
                int b = P >> 12;
                int t = P & 4095;
                float a0 = 1.0f / (1.0f + __expf(s1 - s0));
                out[((b * 2) + 0) * T_DIM + t] = a0;
                out[((b * 2) + 1) * T_DIM + t] = 1.0f - a0;
            }
            __syncthreads();   // sc_s re-zero visible before next tile's atomics
        }
    }
}

extern "C" void kernel_launch(void* const* d_in, const int* in_sizes, int n_in,
                              void* d_out, int out_size) {
    const float* h1 = (const float*)d_in[0];
    const float* h2 = (const float*)d_in[1];
    const float* w  = (const float*)d_in[2];
    const float* v  = (const float*)d_in[3];
    float* out = (float*)d_out;

    cudaFuncSetAttribute(topo_attention_v7,
                         cudaFuncAttributeMaxDynamicSharedMemorySize, SMEM_BYTES);

    int nsm = 148;
    if (cudaDeviceGetAttribute(&nsm, cudaDevAttrMultiProcessorCount, 0) != cudaSuccess || nsm <= 0)
        nsm = 148;

    topo_attention_v7<<<2 * nsm, THREADS, SMEM_BYTES>>>(h1, h2, w, v, out);
}

// round 16
// speedup vs baseline: 1.6425x; 1.1068x over previous
#include <cuda_runtime.h>
#include <cuda_fp16.h>
#include <cstdint>

#define T_DIM 4096
#define NUM_TILES 2048
#define THREADS 256

// ---- shared memory layout (bytes) ----
// VF: v_tp fp16 fragment-packed: [ksg(16)][J(8)][lane(32)][16B = nb-even 8B | nb-odd 8B]
#define VF_OFF 0
// A rings: per group: 3 stages x (64 rows x 128B) ; group stride 24576
#define A_OFF  65536
#define STAGE_BYTES 8192
#define GROUP_RING 24576
#define W_OFF  114688
#define SC_OFF 115200      // 128 floats: [group(2)][row(64)]
#define SMEM_BYTES 115712

__device__ __forceinline__ uint32_t pack2h(float lo, float hi) {
    uint32_t r;
    asm("cvt.rn.f16x2.f32 %0, %1, %2;" : "=r"(r) : "f"(hi), "f"(lo));
    return r;
}

__device__ __forceinline__ float tanh_fast(float x) {
    float r;
    asm("tanh.approx.f32 %0, %1;" : "=f"(r) : "f"(x));
    return r;
}

__device__ __forceinline__ void sts64(uint32_t addr, uint32_t a, uint32_t b) {
    asm volatile("st.shared.v2.b32 [%0], {%1,%2};" :: "r"(addr), "r"(a), "r"(b) : "memory");
}

__device__ __forceinline__ void lds128(uint32_t* r, uint32_t addr) {
    asm volatile("ld.shared.v4.b32 {%0,%1,%2,%3}, [%4];"
                 : "=r"(r[0]), "=r"(r[1]), "=r"(r[2]), "=r"(r[3]) : "r"(addr));
}

__device__ __forceinline__ void mma16(float* c, const uint32_t* a, uint32_t b0, uint32_t b1) {
    asm volatile(
        "mma.sync.aligned.m16n8k16.row.col.f32.f16.f16.f32 "
        "{%0,%1,%2,%3}, {%4,%5,%6,%7}, {%8,%9}, {%0,%1,%2,%3};\n"
        : "+f"(c[0]), "+f"(c[1]), "+f"(c[2]), "+f"(c[3])
        : "r"(a[0]), "r"(a[1]), "r"(a[2]), "r"(a[3]), "r"(b0), "r"(b1));
}

__device__ __forceinline__ void cp_async16(uint32_t saddr, const void* g) {
    asm volatile("cp.async.cg.shared.global [%0], [%1], 16;\n" :: "r"(saddr), "l"(g));
}

__device__ __forceinline__ void bar_grp(int group) {
    asm volatile("bar.sync %0, 128;" :: "r"(group + 1) : "memory");
}

// issue one K=32, 64-row chunk (8KB) for this group: 4 cp.async16 per thread
__device__ __forceinline__ void issue_chunk(int gc, int gtid, int group, uint32_t smem_u32,
                                            const float* h1, const float* h2,
                                            int bx, int grid) {
    int tile = bx + (gc >> 3) * grid;
    int ck = gc & 7;
    uint32_t sbase = smem_u32 + A_OFF + (uint32_t)(group * GROUP_RING + (gc % 3) * STAGE_BYTES);
    #pragma unroll
    for (int i = 0; i < 4; ++i) {
        int idx = i * 128 + gtid;          // 0..511
        int row = idx >> 3;                // 0..63 (local)
        int cell = idx & 7;                // 16B cell within 128B row
        int dcell = cell ^ ((row & 1) << 2);
        const float* hp = (row & 1) ? h2 : h1;
        const float4* src = (const float4*)hp
                            + (size_t)(tile * 64 + group * 32 + (row >> 1)) * 64 + ck * 8 + cell;
        cp_async16(sbase + (uint32_t)(row * 128 + dcell * 16), src);
    }
    asm volatile("cp.async.commit_group;" ::: "memory");
}

__global__ void __launch_bounds__(THREADS, 2)
topo_attention_v8(const float* __restrict__ h1,
                  const float* __restrict__ h2,
                  const float* __restrict__ w,
                  const float* __restrict__ v,
                  float* __restrict__ out) {
    extern __shared__ char smem[];
    uint32_t smem_u32;
    asm("{ .reg .u64 t; cvta.to.shared.u64 t, %1; cvt.u32.u64 %0, t; }"
        : "=r"(smem_u32) : "l"(smem));
    float* w_s  = (float*)(smem + W_OFF);
    float* sc_s = (float*)(smem + SC_OFF);

    const int tid  = threadIdx.x;
    const int bx = blockIdx.x;
    const int grid = gridDim.x;

    // ---- prologue: VF pack (fp16, K-permuted fragment layout), w, sc ----
    for (int i = tid * 4; i < 32768; i += THREADS * 4) {
        float4 vv = *(const float4*)(v + i);
        int l = i >> 8, m = i & 255;
        int ksg = m >> 4, tp = (m >> 2) & 3;
        int nb = l >> 3, gp = l & 7;
        uint32_t addr = smem_u32 + VF_OFF +
            (uint32_t)(ksg * 4096 + (nb >> 1) * 512 + (gp * 4 + tp) * 16 + (nb & 1) * 8);
        sts64(addr, pack2h(vv.x, vv.y), pack2h(vv.z, vv.w));
    }
    if (tid < 128) { w_s[tid] = w[tid]; sc_s[tid] = 0.0f; }
    __syncthreads();

    int ntile = 0;
    for (int t = bx; t < NUM_TILES; t += grid) ntile++;
    const int NCH = ntile * 8;   // K=32 chunks

    // ---- group decomposition: 2 independent 4-warp pipelines ----
    const int group = tid >> 7;       // 0,1
    const int gtid  = tid & 127;
    const int gwid  = gtid >> 5;      // 0..3 within group
    const int lane  = tid & 31;
    const int warp_m = gwid >> 1;     // 2 m-groups of 32 rows
    const int warp_n = gwid & 1;      // 2 n-groups of 64
    const int g   = lane >> 2;
    const int tig = lane & 3;
    const int par = g & 1;

    const uint32_t vb = smem_u32 + VF_OFF + (uint32_t)(warp_n * 2048 + lane * 16);
    const uint32_t ring_base = smem_u32 + A_OFF + (uint32_t)(group * GROUP_RING);
    uint32_t arow[2][2];
    #pragma unroll
    for (int mt = 0; mt < 2; ++mt) {
        int row_lo = warp_m * 32 + mt * 16 + g;   // local row 0..63
        arow[mt][0] = (uint32_t)(row_lo * 128);
        arow[mt][1] = (uint32_t)((row_lo + 8) * 128);
    }

    float acc[2][8][4];
    #pragma unroll
    for (int mt = 0; mt < 2; mt++)
        #pragma unroll
        for (int nt = 0; nt < 8; nt++)
            #pragma unroll
            for (int i = 0; i < 4; i++) acc[mt][nt][i] = 0.0f;

    // prime: stages 0,1
    issue_chunk(0, gtid, group, smem_u32, h1, h2, bx, grid);
    if (NCH > 1) issue_chunk(1, gtid, group, smem_u32, h1, h2, bx, grid);

    for (int gc = 0; gc < NCH; ++gc) {
        // newest commit is chunk min(gc+1, NCH-1): wait depth accordingly
        if (gc + 1 < NCH) {
            asm volatile("cp.async.wait_group 1;" ::: "memory");
        } else {
            asm volatile("cp.async.wait_group 0;" ::: "memory");
        }
        bar_grp(group);   // chunk gc visible group-wide AND group done with MMA(gc-1)

        if (gc + 2 < NCH) issue_chunk(gc + 2, gtid, group, smem_u32, h1, h2, bx, grid);

        uint32_t ab = ring_base + (uint32_t)((gc % 3) * STAGE_BYTES);
        #pragma unroll
        for (int ks = 0; ks < 2; ++ks) {
            int ksg = (gc & 7) * 2 + ks;
            uint32_t bb[4][4];
            #pragma unroll
            for (int jj = 0; jj < 4; ++jj)
                lds128(bb[jj], vb + (uint32_t)(ksg * 4096 + jj * 512));

            int kx = par ? (1 - ks) : ks;
            uint32_t coff = (uint32_t)((kx * 4 + tig) << 4);
            uint32_t afr[2][4];
            #pragma unroll
            for (int mt = 0; mt < 2; ++mt) {
                uint32_t lo[4], hi[4];
                lds128(lo, ab + arow[mt][0] + coff);
                lds128(hi, ab + arow[mt][1] + coff);
                afr[mt][0] = pack2h(__uint_as_float(lo[0]), __uint_as_float(lo[1]));
                afr[mt][1] = pack2h(__uint_as_float(hi[0]), __uint_as_float(hi[1]));
                afr[mt][2] = pack2h(__uint_as_float(lo[2]), __uint_as_float(lo[3]));
                afr[mt][3] = pack2h(__uint_as_float(hi[2]), __uint_as_float(hi[3]));
            }
            #pragma unroll
            for (int mt = 0; mt < 2; ++mt)
                #pragma unroll
                for (int jj = 0; jj < 4; ++jj) {
                    mma16(acc[mt][2 * jj],     afr[mt], bb[jj][0], bb[jj][1]);
                    mma16(acc[mt][2 * jj + 1], afr[mt], bb[jj][2], bb[jj][3]);
                }
        }

        if ((gc & 7) == 7) {
            // ---- group-local epilogue for tile = bx + (gc>>3)*grid ----
            int tile = bx + (gc >> 3) * grid;
            float part[4];
            #pragma unroll
            for (int mt = 0; mt < 2; ++mt) {
                float p0 = 0.f, p1 = 0.f;
                #pragma unroll
                for (int nt = 0; nt < 8; ++nt) {
                    int l0 = warp_n * 64 + nt * 8 + tig * 2;
                    float w0 = w_s[l0], w1 = w_s[l0 + 1];
                    p0 += w0 * tanh_fast(acc[mt][nt][0]) + w1 * tanh_fast(acc[mt][nt][1]);
                    p1 += w0 * tanh_fast(acc[mt][nt][2]) + w1 * tanh_fast(acc[mt][nt][3]);
                    #pragma unroll
                    for (int i = 0; i < 4; i++) acc[mt][nt][i] = 0.0f;
                }
                part[mt * 2] = p0;
                part[mt * 2 + 1] = p1;
            }
            #pragma unroll
            for (int i = 0; i < 4; i++) {
                part[i] += __shfl_xor_sync(0xffffffffu, part[i], 1);
                part[i] += __shfl_xor_sync(0xffffffffu, part[i], 2);
            }
            if (tig == 0) {
                #pragma unroll
                for (int i = 0; i < 4; i++) {
                    int row = warp_m * 32 + (i >> 1) * 16 + (i & 1) * 8 + g;  // local 0..63
                    atomicAdd(&sc_s[group * 64 + row], part[i]);
                }
            }
            bar_grp(group);   // group's atomicAdds visible
            if (gtid < 32) {
                float s0 = sc_s[group * 64 + 2 * gtid];
                float s1 = sc_s[group * 64 + 2 * gtid + 1];
                sc_s[group * 64 + 2 * gtid] = 0.0f;
                sc_s[group * 64 + 2 * gtid + 1] = 0.0f;
                int P = tile * 64 + group * 32 + gtid;    // global (b*T + t)
                int b = P >> 12;
                int t = P & 4095;
                float a0 = 1.0f / (1.0f + __expf(s1 - s0));
                out[((b * 2) + 0) * T_DIM + t] = a0;
                out[((b * 2) + 1) * T_DIM + t] = 1.0f - a0;
            }
            bar_grp(group);   // re-zero visible before next tile's atomics
        }
    }
}

extern "C" void kernel_launch(void* const* d_in, const int* in_sizes, int n_in,
                              void* d_out, int out_size) {
    const float* h1 = (const float*)d_in[0];
    const float* h2 = (const float*)d_in[1];
    const float* w  = (const float*)d_in[2];
    const float* v  = (const float*)d_in[3];
    float* out = (float*)d_out;

    cudaFuncSetAttribute(topo_attention_v8,
                         cudaFuncAttributeMaxDynamicSharedMemorySize, SMEM_BYTES);

    int nsm = 148;
    if (cudaDeviceGetAttribute(&nsm, cudaDevAttrMultiProcessorCount, 0) != cudaSuccess || nsm <= 0)
        nsm = 148;

    topo_attention_v8<<<2 * nsm, THREADS, SMEM_BYTES>>>(h1, h2, w, v, out);
}